// round 2
// baseline (speedup 1.0000x reference)
#include <cuda_runtime.h>

#define N_NODES 50000
#define N_EDGES 800000
#define IN_CH   256
#define HID_CH  256
#define OUT_CH  128

// ---------------- scratch (no allocs allowed -> __device__ globals) ----------
__device__ float g_deg [N_NODES];
__device__ float g_dinv[N_NODES];
__device__ float g_xw  [(size_t)N_NODES * HID_CH];  // x @ W1
__device__ float g_agg1[(size_t)N_NODES * HID_CH];  // agg of xw, then relu'd h (in place)
__device__ float g_agg2[(size_t)N_NODES * HID_CH];  // agg of h

// ---------------- degree / normalization ------------------------------------
__global__ void k_deg_init() {
    int i = blockIdx.x * blockDim.x + threadIdx.x;
    if (i < N_NODES) g_deg[i] = 1.0f;   // self-loop
}

__global__ void k_deg_edges(const int* __restrict__ ei) {
    int e = blockIdx.x * blockDim.x + threadIdx.x;
    if (e < N_EDGES) atomicAdd(&g_deg[ei[N_EDGES + e]], 1.0f);
}

__global__ void k_dinv() {
    int i = blockIdx.x * blockDim.x + threadIdx.x;
    if (i < N_NODES) g_dinv[i] = rsqrtf(g_deg[i]);  // deg >= 1 always
}

// ---------------- SGEMM: C = A[M,K] @ B[K,Nn] (+bias) -----------------------
// If C2 != nullptr, additionally writes C2[i,j] = raw[i,j] * dinv[i]^2
// (self-loop contribution initializing the aggregation buffer).
// BM=128, BN=64, BK=16, TM=8, TN=4, 256 threads.
__global__ void k_sgemm(const float* __restrict__ A, const float* __restrict__ B,
                        float* __restrict__ C, int M, int Nn, int K,
                        const float* __restrict__ bias,
                        float* __restrict__ C2)
{
    __shared__ float As[16][132];   // [BK][BM+4] pad to break bank conflicts
    __shared__ float Bs[16][64];

    const int t  = threadIdx.x;
    const int bm = blockIdx.y * 128;
    const int bn = blockIdx.x * 64;
    const int tx = t & 15;          // 16 col-threads
    const int ty = t >> 4;          // 16 row-threads

    float acc[8][4];
#pragma unroll
    for (int i = 0; i < 8; i++)
#pragma unroll
        for (int j = 0; j < 4; j++) acc[i][j] = 0.0f;

    for (int k0 = 0; k0 < K; k0 += 16) {
        // A tile: 128x16 = 2048 elems, 8 per thread
#pragma unroll
        for (int i = 0; i < 8; i++) {
            int idx = t + i * 256;
            int r = idx >> 4;
            int c = idx & 15;
            int gr = bm + r;
            As[c][r] = (gr < M) ? A[(size_t)gr * K + k0 + c] : 0.0f;
        }
        // B tile: 16x64 = 1024 elems, 4 per thread
#pragma unroll
        for (int i = 0; i < 4; i++) {
            int idx = t + i * 256;
            int r = idx >> 6;
            int c = idx & 63;
            Bs[r][c] = B[(size_t)(k0 + r) * Nn + bn + c];
        }
        __syncthreads();

#pragma unroll
        for (int k = 0; k < 16; k++) {
            float ra[8], rb[4];
#pragma unroll
            for (int i = 0; i < 8; i++) ra[i] = As[k][ty * 8 + i];
#pragma unroll
            for (int j = 0; j < 4; j++) rb[j] = Bs[k][tx * 4 + j];
#pragma unroll
            for (int i = 0; i < 8; i++)
#pragma unroll
                for (int j = 0; j < 4; j++)
                    acc[i][j] = fmaf(ra[i], rb[j], acc[i][j]);
        }
        __syncthreads();
    }

#pragma unroll
    for (int i = 0; i < 8; i++) {
        int gr = bm + ty * 8 + i;
        if (gr >= M) continue;
        float dd = 0.0f;
        if (C2) { float di = g_dinv[gr]; dd = di * di; }
#pragma unroll
        for (int j = 0; j < 4; j++) {
            int gc = bn + tx * 4 + j;
            float v = acc[i][j];
            C[(size_t)gr * Nn + gc] = bias ? (v + bias[gc]) : v;
            if (C2) C2[(size_t)gr * Nn + gc] = v * dd;
        }
    }
}

// ---------------- edge scatter-add aggregation (one warp per edge) ----------
// which==0: g_xw  -> g_agg1 ; which==1: g_agg1(h) -> g_agg2
__global__ void k_agg(const int* __restrict__ ei, int which)
{
    const float* __restrict__ in  = which ? g_agg1 : g_xw;
    float* __restrict__       out = which ? g_agg2 : g_agg1;

    int w    = (blockIdx.x * blockDim.x + threadIdx.x) >> 5;
    int lane = threadIdx.x & 31;
    if (w >= N_EDGES) return;

    int s = ei[w];
    int d = ei[N_EDGES + w];
    float nrm = g_dinv[s] * g_dinv[d];

    const float* sp = in  + (size_t)s * HID_CH;
    float*       dp = out + (size_t)d * HID_CH;
#pragma unroll
    for (int c = lane; c < HID_CH; c += 32)
        atomicAdd(&dp[c], nrm * sp[c]);
}

// ---------------- relu + bias + init of second aggregation ------------------
__global__ void k_finalize(const float* __restrict__ b1)
{
    size_t i = (size_t)blockIdx.x * blockDim.x + threadIdx.x;
    if (i >= (size_t)N_NODES * HID_CH) return;
    int c = (int)(i & (HID_CH - 1));
    int r = (int)(i >> 8);           // HID_CH == 256
    float v = fmaxf(g_agg1[i] + b1[c], 0.0f);
    g_agg1[i] = v;                   // h (in place)
    float di = g_dinv[r];
    g_agg2[i] = v * di * di;         // self-loop init for second agg
}

// ---------------- launch ----------------------------------------------------
extern "C" void kernel_launch(void* const* d_in, const int* in_sizes, int n_in,
                              void* d_out, int out_size)
{
    const float* x   = (const float*)d_in[0];
    const int*   ei  = (const int*)d_in[1];      // JAX default x64-disabled -> int32
    const float* W1  = (const float*)d_in[2];
    const float* b1  = (const float*)d_in[3];
    const float* Wmu = (const float*)d_in[4];
    const float* bmu = (const float*)d_in[5];
    const float* Wls = (const float*)d_in[6];
    const float* bls = (const float*)d_in[7];
    float*       out = (float*)d_out;

    float *p_xw, *p_agg1, *p_agg2;
    cudaGetSymbolAddress((void**)&p_xw,   g_xw);
    cudaGetSymbolAddress((void**)&p_agg1, g_agg1);
    cudaGetSymbolAddress((void**)&p_agg2, g_agg2);

    // 1. normalization coefficients
    k_deg_init <<<(N_NODES + 255) / 256, 256>>>();
    k_deg_edges<<<(N_EDGES + 255) / 256, 256>>>(ei);
    k_dinv     <<<(N_NODES + 255) / 256, 256>>>();

    // 2. XW = x @ W1 ; agg1 init = XW * dinv^2 (self loop)
    {
        dim3 grid(HID_CH / 64, (N_NODES + 127) / 128);
        k_sgemm<<<grid, 256>>>(x, W1, p_xw, N_NODES, HID_CH, IN_CH, nullptr, p_agg1);
    }

    // 3. edge aggregation into agg1
    k_agg<<<(N_EDGES * 32) / 256, 256>>>(ei, 0);

    // 4. h = relu(agg1 + b1); agg2 init = h * dinv^2
    k_finalize<<<((size_t)N_NODES * HID_CH + 255) / 256, 256>>>(b1);

    // 5. edge aggregation of h into agg2  (agg(h@W) == agg(h)@W -> do it once)
    k_agg<<<(N_EDGES * 32) / 256, 256>>>(ei, 1);

    // 6. mu = agg2 @ Wmu + bmu ; logstd = agg2 @ Wls + bls
    {
        dim3 grid(OUT_CH / 64, (N_NODES + 127) / 128);
        k_sgemm<<<grid, 256>>>(p_agg2, Wmu, out, N_NODES, OUT_CH, HID_CH, bmu, nullptr);
        k_sgemm<<<grid, 256>>>(p_agg2, Wls, out + (size_t)N_NODES * OUT_CH,
                               N_NODES, OUT_CH, HID_CH, bls, nullptr);
    }
}

// round 3
// speedup vs baseline: 1.2545x; 1.2545x over previous
#include <cuda_runtime.h>

#define N_NODES 50000
#define N_EDGES 800000
#define IN_CH   256
#define HID_CH  256
#define OUT_CH  128

// ---------------- scratch (no allocs allowed -> __device__ globals) ----------
__device__ float g_deg [N_NODES];
__device__ float g_dinv[N_NODES];
__device__ float g_xw  [(size_t)N_NODES * HID_CH];  // x @ W1
__device__ float g_agg1[(size_t)N_NODES * HID_CH];  // agg of xw, then relu'd h (in place)
__device__ float g_agg2[(size_t)N_NODES * HID_CH];  // agg of h

// ---------------- vector reduction helper (sm_90+) --------------------------
__device__ __forceinline__ void red_add_v4(float* p, float a, float b, float c, float d) {
    asm volatile("red.global.add.v4.f32 [%0], {%1, %2, %3, %4};"
                 :: "l"(p), "f"(a), "f"(b), "f"(c), "f"(d) : "memory");
}

// ---------------- degree / normalization ------------------------------------
__global__ void k_deg_init() {
    int i = blockIdx.x * blockDim.x + threadIdx.x;
    if (i < N_NODES) g_deg[i] = 1.0f;   // self-loop
}

__global__ void k_deg_edges(const int* __restrict__ ei) {
    int e = blockIdx.x * blockDim.x + threadIdx.x;
    if (e < N_EDGES) atomicAdd(&g_deg[ei[N_EDGES + e]], 1.0f);
}

__global__ void k_dinv() {
    int i = blockIdx.x * blockDim.x + threadIdx.x;
    if (i < N_NODES) g_dinv[i] = rsqrtf(g_deg[i]);  // deg >= 1 always
}

// ---------------- SGEMM: C = A[M,K] @ B[K,Nn] (+bias) -----------------------
// BM=128, BN=128, BK=16, TM=8, TN=8, 256 threads (16x16).
// If C2 != nullptr, additionally writes C2[i,j] = raw[i,j] * dinv[i]^2.
// Requires: Nn % 128 == 0, K % 16 == 0 (true for all 3 GEMMs here).
__global__ void __launch_bounds__(256)
k_sgemm(const float* __restrict__ A, const float* __restrict__ B,
        float* __restrict__ C, int M, int Nn, int K,
        const float* __restrict__ bias, float* __restrict__ C2)
{
    __shared__ float As[16][128];   // [k][m]
    __shared__ float Bs[16][128];   // [k][n]

    const int t  = threadIdx.x;
    const int bm = blockIdx.y * 128;
    const int bn = blockIdx.x * 128;
    const int tx = t & 15;          // 16 col-threads (8 cols each)
    const int ty = t >> 4;          // 16 row-threads (8 rows each)

    float acc[8][8];
#pragma unroll
    for (int i = 0; i < 8; i++)
#pragma unroll
        for (int j = 0; j < 8; j++) acc[i][j] = 0.0f;

    for (int k0 = 0; k0 < K; k0 += 16) {
        // --- A tile: 128 rows x 16 k = 512 float4, 2 per thread ---
#pragma unroll
        for (int i = 0; i < 2; i++) {
            int f   = t + i * 256;
            int row = f >> 2;          // 4 float4 per row
            int kq  = f & 3;
            int gr  = bm + row;
            float4 v = make_float4(0.f, 0.f, 0.f, 0.f);
            if (gr < M)
                v = *reinterpret_cast<const float4*>(&A[(size_t)gr * K + k0 + kq * 4]);
            As[kq * 4 + 0][row] = v.x;
            As[kq * 4 + 1][row] = v.y;
            As[kq * 4 + 2][row] = v.z;
            As[kq * 4 + 3][row] = v.w;
        }
        // --- B tile: 16 k x 128 n = 512 float4, 2 per thread ---
#pragma unroll
        for (int i = 0; i < 2; i++) {
            int f    = t + i * 256;
            int row  = f >> 5;         // 32 float4 per row
            int col4 = f & 31;
            float4 v = *reinterpret_cast<const float4*>(
                &B[(size_t)(k0 + row) * Nn + bn + col4 * 4]);
            *reinterpret_cast<float4*>(&Bs[row][col4 * 4]) = v;
        }
        __syncthreads();

#pragma unroll
        for (int k = 0; k < 16; k++) {
            float4 a0 = *reinterpret_cast<const float4*>(&As[k][ty * 8]);
            float4 a1 = *reinterpret_cast<const float4*>(&As[k][ty * 8 + 4]);
            float4 b0 = *reinterpret_cast<const float4*>(&Bs[k][tx * 8]);
            float4 b1 = *reinterpret_cast<const float4*>(&Bs[k][tx * 8 + 4]);
            float ra[8] = {a0.x, a0.y, a0.z, a0.w, a1.x, a1.y, a1.z, a1.w};
            float rb[8] = {b0.x, b0.y, b0.z, b0.w, b1.x, b1.y, b1.z, b1.w};
#pragma unroll
            for (int i = 0; i < 8; i++)
#pragma unroll
                for (int j = 0; j < 8; j++)
                    acc[i][j] = fmaf(ra[i], rb[j], acc[i][j]);
        }
        __syncthreads();
    }

    // --- epilogue ---
    float bvals[8];
#pragma unroll
    for (int j = 0; j < 8; j++) bvals[j] = bias ? bias[bn + tx * 8 + j] : 0.0f;

#pragma unroll
    for (int i = 0; i < 8; i++) {
        int gr = bm + ty * 8 + i;
        if (gr >= M) continue;
        float dd = 0.0f;
        if (C2) { float di = g_dinv[gr]; dd = di * di; }
        float* crow = &C[(size_t)gr * Nn + bn + tx * 8];
        float4 c0 = make_float4(acc[i][0] + bvals[0], acc[i][1] + bvals[1],
                                acc[i][2] + bvals[2], acc[i][3] + bvals[3]);
        float4 c1 = make_float4(acc[i][4] + bvals[4], acc[i][5] + bvals[5],
                                acc[i][6] + bvals[6], acc[i][7] + bvals[7]);
        reinterpret_cast<float4*>(crow)[0] = c0;
        reinterpret_cast<float4*>(crow)[1] = c1;
        if (C2) {
            float* c2row = &C2[(size_t)gr * Nn + bn + tx * 8];
            float4 d0 = make_float4(acc[i][0] * dd, acc[i][1] * dd,
                                    acc[i][2] * dd, acc[i][3] * dd);
            float4 d1 = make_float4(acc[i][4] * dd, acc[i][5] * dd,
                                    acc[i][6] * dd, acc[i][7] * dd);
            reinterpret_cast<float4*>(c2row)[0] = d0;
            reinterpret_cast<float4*>(c2row)[1] = d1;
        }
    }
}

// ---------------- edge scatter-add aggregation (one warp per edge) ----------
// which==0: g_xw -> g_agg1 ; which==1: g_agg1(h) -> g_agg2
// float4 gather + red.global.add.v4.f32 scatter: 2 loads + 2 reds per lane.
__global__ void k_agg(const int* __restrict__ ei, int which)
{
    const float* __restrict__ inp = which ? g_agg1 : g_xw;
    float* __restrict__       out = which ? g_agg2 : g_agg1;

    int w    = (blockIdx.x * blockDim.x + threadIdx.x) >> 5;
    int lane = threadIdx.x & 31;
    if (w >= N_EDGES) return;

    int s = ei[w];
    int d = ei[N_EDGES + w];
    float nrm = g_dinv[s] * g_dinv[d];

    const float4* sp = reinterpret_cast<const float4*>(inp + (size_t)s * HID_CH);
    float*        dp = out + (size_t)d * HID_CH;

#pragma unroll
    for (int c = 0; c < 2; c++) {          // 64 float4 per row / 32 lanes
        int idx = lane + c * 32;
        float4 v = sp[idx];
        red_add_v4(dp + idx * 4, v.x * nrm, v.y * nrm, v.z * nrm, v.w * nrm);
    }
}

// ---------------- relu + bias + init of second aggregation ------------------
__global__ void k_finalize(const float* __restrict__ b1)
{
    size_t q = (size_t)blockIdx.x * blockDim.x + threadIdx.x;   // float4 index
    if (q >= (size_t)N_NODES * HID_CH / 4) return;
    int c4 = (int)(q & 63);          // 64 float4 per row
    int r  = (int)(q >> 6);
    float4 v = reinterpret_cast<float4*>(g_agg1)[q];
    const float4 bb = reinterpret_cast<const float4*>(b1)[c4];
    v.x = fmaxf(v.x + bb.x, 0.0f);
    v.y = fmaxf(v.y + bb.y, 0.0f);
    v.z = fmaxf(v.z + bb.z, 0.0f);
    v.w = fmaxf(v.w + bb.w, 0.0f);
    reinterpret_cast<float4*>(g_agg1)[q] = v;          // h (in place)
    float di = g_dinv[r];
    float dd = di * di;
    float4 o = make_float4(v.x * dd, v.y * dd, v.z * dd, v.w * dd);
    reinterpret_cast<float4*>(g_agg2)[q] = o;          // self-loop init
}

// ---------------- launch ----------------------------------------------------
extern "C" void kernel_launch(void* const* d_in, const int* in_sizes, int n_in,
                              void* d_out, int out_size)
{
    const float* x   = (const float*)d_in[0];
    const int*   ei  = (const int*)d_in[1];      // int32 (JAX default x64 disabled)
    const float* W1  = (const float*)d_in[2];
    const float* b1  = (const float*)d_in[3];
    const float* Wmu = (const float*)d_in[4];
    const float* bmu = (const float*)d_in[5];
    const float* Wls = (const float*)d_in[6];
    const float* bls = (const float*)d_in[7];
    float*       out = (float*)d_out;

    float *p_xw, *p_agg1, *p_agg2;
    cudaGetSymbolAddress((void**)&p_xw,   g_xw);
    cudaGetSymbolAddress((void**)&p_agg1, g_agg1);
    cudaGetSymbolAddress((void**)&p_agg2, g_agg2);

    // 1. normalization coefficients
    k_deg_init <<<(N_NODES + 255) / 256, 256>>>();
    k_deg_edges<<<(N_EDGES + 255) / 256, 256>>>(ei);
    k_dinv     <<<(N_NODES + 255) / 256, 256>>>();

    // 2. XW = x @ W1 ; agg1 init = XW * dinv^2 (self loop)
    {
        dim3 grid(HID_CH / 128, (N_NODES + 127) / 128);
        k_sgemm<<<grid, 256>>>(x, W1, p_xw, N_NODES, HID_CH, IN_CH, nullptr, p_agg1);
    }

    // 3. edge aggregation into agg1
    k_agg<<<(N_EDGES * 32) / 256, 256>>>(ei, 0);

    // 4. h = relu(agg1 + b1); agg2 init = h * dinv^2
    k_finalize<<<((size_t)N_NODES * HID_CH / 4 + 255) / 256, 256>>>(b1);

    // 5. edge aggregation of h into agg2  (agg(h@W) == agg(h)@W -> do it once)
    k_agg<<<(N_EDGES * 32) / 256, 256>>>(ei, 1);

    // 6. mu = agg2 @ Wmu + bmu ; logstd = agg2 @ Wls + bls
    {
        dim3 grid(OUT_CH / 128, (N_NODES + 127) / 128);
        k_sgemm<<<grid, 256>>>(p_agg2, Wmu, out, N_NODES, OUT_CH, HID_CH, bmu, nullptr);
        k_sgemm<<<grid, 256>>>(p_agg2, Wls, out + (size_t)N_NODES * OUT_CH,
                               N_NODES, OUT_CH, HID_CH, bls, nullptr);
    }
}

// round 5
// speedup vs baseline: 1.7318x; 1.3805x over previous
#include <cuda_runtime.h>
#include <cuda_bf16.h>
#include <cstdint>

#define N_NODES 50000
#define N_EDGES 800000
#define IN_CH   256
#define HID_CH  256
#define OUT_CH  128

// ---------------- scratch (__device__ globals, no allocs) --------------------
__device__ float g_deg [N_NODES];
__device__ float g_dinv[N_NODES];
__device__ float g_xw  [(size_t)N_NODES * HID_CH];
__device__ float g_agg1[(size_t)N_NODES * HID_CH];
__device__ float g_agg2[(size_t)N_NODES * HID_CH];
__device__ __nv_bfloat16 gA_hi[(size_t)N_NODES * IN_CH];
__device__ __nv_bfloat16 gA_lo[(size_t)N_NODES * IN_CH];
__device__ __nv_bfloat16 gB1_hi[IN_CH * HID_CH];   // W1^T  [n][k]
__device__ __nv_bfloat16 gB1_lo[IN_CH * HID_CH];
__device__ __nv_bfloat16 gB2_hi[HID_CH * HID_CH];  // [Wmu|Wls]^T [n][k]
__device__ __nv_bfloat16 gB2_lo[HID_CH * HID_CH];
__device__ float g_bcat[256];

// ---------------- helpers ----------------------------------------------------
__device__ __forceinline__ uint32_t smem_u32(const void* p) {
    uint32_t a;
    asm("{ .reg .u64 t; cvta.to.shared.u64 t, %1; cvt.u32.u64 %0, t; }" : "=r"(a) : "l"(p));
    return a;
}
__device__ __forceinline__ uint32_t sw128(uint32_t off) { return off ^ ((off >> 3) & 0x70); }

#define LDSM_X4(r, addr) \
    asm volatile("ldmatrix.sync.aligned.m8n8.x4.shared.b16 {%0,%1,%2,%3}, [%4];" \
                 : "=r"((r)[0]), "=r"((r)[1]), "=r"((r)[2]), "=r"((r)[3]) : "r"(addr))
#define LDSM_X2(r, addr) \
    asm volatile("ldmatrix.sync.aligned.m8n8.x2.shared.b16 {%0,%1}, [%2];" \
                 : "=r"((r)[0]), "=r"((r)[1]) : "r"(addr))

__device__ __forceinline__ void mma_bf16(float* c, const uint32_t* a, const uint32_t* b) {
    asm volatile(
        "mma.sync.aligned.m16n8k16.row.col.f32.bf16.bf16.f32 "
        "{%0,%1,%2,%3}, {%4,%5,%6,%7}, {%8,%9}, {%0,%1,%2,%3};"
        : "+f"(c[0]), "+f"(c[1]), "+f"(c[2]), "+f"(c[3])
        : "r"(a[0]), "r"(a[1]), "r"(a[2]), "r"(a[3]), "r"(b[0]), "r"(b[1]));
}

__device__ __forceinline__ void red_add_v4(float* p, float a, float b, float c, float d) {
    asm volatile("red.global.add.v4.f32 [%0], {%1, %2, %3, %4};"
                 :: "l"(p), "f"(a), "f"(b), "f"(c), "f"(d) : "memory");
}

// ---------------- degree / normalization ------------------------------------
__global__ void k_deg_init() {
    int i = blockIdx.x * blockDim.x + threadIdx.x;
    if (i < N_NODES) g_deg[i] = 1.0f;
}
__global__ void k_deg_edges(const int* __restrict__ ei) {
    int e = blockIdx.x * blockDim.x + threadIdx.x;
    if (e < N_EDGES) atomicAdd(&g_deg[ei[N_EDGES + e]], 1.0f);
}
__global__ void k_dinv() {
    int i = blockIdx.x * blockDim.x + threadIdx.x;
    if (i < N_NODES) g_dinv[i] = rsqrtf(g_deg[i]);
}

// ---------------- fp32 -> bf16 hi/lo split (Dekker) --------------------------
__global__ void k_split(const float* __restrict__ src, size_t n4) {
    size_t q = (size_t)blockIdx.x * blockDim.x + threadIdx.x;
    if (q >= n4) return;
    float4 v = reinterpret_cast<const float4*>(src)[q];
    __nv_bfloat16 hx = __float2bfloat16(v.x), hy = __float2bfloat16(v.y);
    __nv_bfloat16 hz = __float2bfloat16(v.z), hw = __float2bfloat16(v.w);
    __nv_bfloat162* H = reinterpret_cast<__nv_bfloat162*>(gA_hi);
    __nv_bfloat162* L = reinterpret_cast<__nv_bfloat162*>(gA_lo);
    H[q * 2 + 0] = __nv_bfloat162(hx, hy);
    H[q * 2 + 1] = __nv_bfloat162(hz, hw);
    L[q * 2 + 0] = __nv_bfloat162(__float2bfloat16(v.x - __bfloat162float(hx)),
                                  __float2bfloat16(v.y - __bfloat162float(hy)));
    L[q * 2 + 1] = __nv_bfloat162(__float2bfloat16(v.z - __bfloat162float(hz)),
                                  __float2bfloat16(v.w - __bfloat162float(hw)));
}

// W1 [K=256][N=256] -> gB1 [n][k] (transposed, split)
__global__ void k_prepW1(const float* __restrict__ W) {
    int idx = blockIdx.x * blockDim.x + threadIdx.x;
    if (idx >= 256 * 256) return;
    int n = idx >> 8, k = idx & 255;
    float v = W[k * 256 + n];
    __nv_bfloat16 h = __float2bfloat16(v);
    gB1_hi[idx] = h;
    gB1_lo[idx] = __float2bfloat16(v - __bfloat162float(h));
}

// [Wmu|Wls] (each [256][128]) -> gB2 [n][k]; also bias concat
__global__ void k_prepW2(const float* __restrict__ Wmu, const float* __restrict__ Wls,
                         const float* __restrict__ bmu, const float* __restrict__ bls) {
    int idx = blockIdx.x * blockDim.x + threadIdx.x;
    if (idx >= 256 * 256) return;
    int n = idx >> 8, k = idx & 255;
    float v = (n < 128) ? Wmu[k * 128 + n] : Wls[k * 128 + (n - 128)];
    __nv_bfloat16 h = __float2bfloat16(v);
    gB2_hi[idx] = h;
    gB2_lo[idx] = __float2bfloat16(v - __bfloat162float(h));
    if (k == 0) g_bcat[n] = (n < 128) ? bmu[n] : bls[n - 128];
}

// ---------------- mma.sync GEMM: C[M,256] = A[M,256] @ B^T --------------------
// CTA 128x128, BK=64, 8 warps (2x4), warp tile 64x32.
// A/B fp32 values pre-split into bf16 hi/lo; 3 MMAs per k16 recover ~fp32.
// mode 0: out0 = raw (xw, stride 256), out1 = raw*dinv^2 (agg init).
// mode 1: column block 0 -> out0 (+bias), block 1 -> out1 (+bias), stride 128.
#define SM_AHI 0u
#define SM_ALO 16384u
#define SM_BHI 32768u
#define SM_BLO 49152u
#define SM_TOT 65536

__global__ void __launch_bounds__(256, 1)
k_mma_gemm(const __nv_bfloat16* __restrict__ Ahi, const __nv_bfloat16* __restrict__ Alo,
           const __nv_bfloat16* __restrict__ Bhi, const __nv_bfloat16* __restrict__ Blo,
           int M, int mode,
           float* __restrict__ out0, float* __restrict__ out1,
           const float* __restrict__ bias)
{
    extern __shared__ char smem[];
    const uint32_t sb = smem_u32(smem);
    const int tid = threadIdx.x, lane = tid & 31, wid = tid >> 5;
    const int wm = wid >> 2, wn = wid & 3;           // 2 x 4 warp grid
    const int bm = blockIdx.y * 128, bn = blockIdx.x * 128;

    float acc[4][4][4];
#pragma unroll
    for (int f = 0; f < 4; f++)
#pragma unroll
        for (int g = 0; g < 4; g++)
#pragma unroll
            for (int r = 0; r < 4; r++) acc[f][g][r] = 0.0f;

    for (int ch = 0; ch < 4; ch++) {
        const int k0 = ch * 64;
        // ---- load tiles: 128 rows x 64 bf16 (128B rows, SW128) x4 buffers ----
#pragma unroll
        for (int i = 0; i < 4; i++) {
            int u = tid + i * 256;
            int row = u >> 3, j = u & 7;
            uint32_t dst = sw128(row * 128 + j * 16);
            uint4 vh = make_uint4(0, 0, 0, 0), vl = make_uint4(0, 0, 0, 0);
            if (bm + row < M) {
                vh = *reinterpret_cast<const uint4*>(Ahi + (size_t)(bm + row) * 256 + k0 + j * 8);
                vl = *reinterpret_cast<const uint4*>(Alo + (size_t)(bm + row) * 256 + k0 + j * 8);
            }
            *reinterpret_cast<uint4*>(smem + SM_AHI + dst) = vh;
            *reinterpret_cast<uint4*>(smem + SM_ALO + dst) = vl;
            *reinterpret_cast<uint4*>(smem + SM_BHI + dst) =
                *reinterpret_cast<const uint4*>(Bhi + (size_t)(bn + row) * 256 + k0 + j * 8);
            *reinterpret_cast<uint4*>(smem + SM_BLO + dst) =
                *reinterpret_cast<const uint4*>(Blo + (size_t)(bn + row) * 256 + k0 + j * 8);
        }
        __syncthreads();

#pragma unroll
        for (int s = 0; s < 4; s++) {                // k16 steps within BK=64
            uint32_t ah[4][4], al[4][4], bh[4][2], bl[4][2];
#pragma unroll
            for (int f = 0; f < 4; f++) {
                int row = wm * 64 + f * 16 + (lane & 15);
                int kb  = s * 32 + (lane >> 4) * 16;
                uint32_t ad = sw128((uint32_t)(row * 128 + kb));
                LDSM_X4(ah[f], sb + SM_AHI + ad);
                LDSM_X4(al[f], sb + SM_ALO + ad);
            }
#pragma unroll
            for (int g = 0; g < 4; g++) {
                int row = wn * 32 + g * 8 + (lane & 7);
                int kb  = s * 32 + ((lane >> 3) & 1) * 16;
                uint32_t ad = sw128((uint32_t)(row * 128 + kb));
                LDSM_X2(bh[g], sb + SM_BHI + ad);
                LDSM_X2(bl[g], sb + SM_BLO + ad);
            }
#pragma unroll
            for (int f = 0; f < 4; f++)
#pragma unroll
                for (int g = 0; g < 4; g++) {
                    mma_bf16(acc[f][g], ah[f], bh[g]);
                    mma_bf16(acc[f][g], al[f], bh[g]);
                    mma_bf16(acc[f][g], ah[f], bl[g]);
                }
        }
        __syncthreads();
    }

    // ---- epilogue ----
#pragma unroll
    for (int f = 0; f < 4; f++) {
        int r0 = bm + wm * 64 + f * 16 + (lane >> 2);
#pragma unroll
        for (int half = 0; half < 2; half++) {
            int gr = r0 + half * 8;
            if (gr >= M) continue;
            float dd = 0.0f;
            if (mode == 0) { float di = g_dinv[gr]; dd = di * di; }
#pragma unroll
            for (int g = 0; g < 4; g++) {
                int col = bn + wn * 32 + g * 8 + (lane & 3) * 2;
                float v0 = acc[f][g][half * 2 + 0];
                float v1 = acc[f][g][half * 2 + 1];
                if (mode == 0) {
                    float2* d0 = reinterpret_cast<float2*>(out0 + (size_t)gr * 256 + col);
                    float2* d1 = reinterpret_cast<float2*>(out1 + (size_t)gr * 256 + col);
                    *d0 = make_float2(v0, v1);
                    *d1 = make_float2(v0 * dd, v1 * dd);
                } else {
                    float* base = (bn == 0) ? out0 : out1;
                    int cl = col - bn;
                    float2* d = reinterpret_cast<float2*>(base + (size_t)gr * 128 + cl);
                    *d = make_float2(v0 + bias[col], v1 + bias[col + 1]);
                }
            }
        }
    }
}

// ---------------- edge scatter-add aggregation (one warp per edge) ----------
__global__ void k_agg(const int* __restrict__ ei, int which)
{
    const float* __restrict__ inp = which ? g_agg1 : g_xw;
    float* __restrict__       out = which ? g_agg2 : g_agg1;

    int w    = (blockIdx.x * blockDim.x + threadIdx.x) >> 5;
    int lane = threadIdx.x & 31;
    if (w >= N_EDGES) return;

    int s = ei[w];
    int d = ei[N_EDGES + w];
    float nrm = g_dinv[s] * g_dinv[d];

    const float4* sp = reinterpret_cast<const float4*>(inp + (size_t)s * HID_CH);
    float*        dp = out + (size_t)d * HID_CH;
#pragma unroll
    for (int c = 0; c < 2; c++) {
        int idx = lane + c * 32;
        float4 v = sp[idx];
        red_add_v4(dp + idx * 4, v.x * nrm, v.y * nrm, v.z * nrm, v.w * nrm);
    }
}

// ---------------- relu + bias + init of second aggregation ------------------
__global__ void k_finalize(const float* __restrict__ b1)
{
    size_t q = (size_t)blockIdx.x * blockDim.x + threadIdx.x;
    if (q >= (size_t)N_NODES * HID_CH / 4) return;
    int c4 = (int)(q & 63);
    int r  = (int)(q >> 6);
    float4 v = reinterpret_cast<float4*>(g_agg1)[q];
    const float4 bb = reinterpret_cast<const float4*>(b1)[c4];
    v.x = fmaxf(v.x + bb.x, 0.0f);
    v.y = fmaxf(v.y + bb.y, 0.0f);
    v.z = fmaxf(v.z + bb.z, 0.0f);
    v.w = fmaxf(v.w + bb.w, 0.0f);
    reinterpret_cast<float4*>(g_agg1)[q] = v;
    float di = g_dinv[r], dd = di * di;
    reinterpret_cast<float4*>(g_agg2)[q] = make_float4(v.x * dd, v.y * dd, v.z * dd, v.w * dd);
}

// ---------------- launch ----------------------------------------------------
extern "C" void kernel_launch(void* const* d_in, const int* in_sizes, int n_in,
                              void* d_out, int out_size)
{
    const float* x   = (const float*)d_in[0];
    const int*   ei  = (const int*)d_in[1];
    const float* W1  = (const float*)d_in[2];
    const float* b1  = (const float*)d_in[3];
    const float* Wmu = (const float*)d_in[4];
    const float* bmu = (const float*)d_in[5];
    const float* Wls = (const float*)d_in[6];
    const float* bls = (const float*)d_in[7];
    float*       out = (float*)d_out;

    float *p_xw, *p_agg1, *p_agg2, *p_bcat;
    __nv_bfloat16 *pAh, *pAl, *pB1h, *pB1l, *pB2h, *pB2l;
    cudaGetSymbolAddress((void**)&p_xw,   g_xw);
    cudaGetSymbolAddress((void**)&p_agg1, g_agg1);
    cudaGetSymbolAddress((void**)&p_agg2, g_agg2);
    cudaGetSymbolAddress((void**)&p_bcat, g_bcat);
    cudaGetSymbolAddress((void**)&pAh,  gA_hi);
    cudaGetSymbolAddress((void**)&pAl,  gA_lo);
    cudaGetSymbolAddress((void**)&pB1h, gB1_hi);
    cudaGetSymbolAddress((void**)&pB1l, gB1_lo);
    cudaGetSymbolAddress((void**)&pB2h, gB2_hi);
    cudaGetSymbolAddress((void**)&pB2l, gB2_lo);

    cudaFuncSetAttribute(k_mma_gemm, cudaFuncAttributeMaxDynamicSharedMemorySize, SM_TOT);

    const size_t n4 = (size_t)N_NODES * HID_CH / 4;
    dim3 gemm_grid(2, (N_NODES + 127) / 128);       // N=256 fused, M blocks

    // 1. normalization
    k_deg_init <<<(N_NODES + 255) / 256, 256>>>();
    k_deg_edges<<<(N_EDGES + 255) / 256, 256>>>(ei);
    k_dinv     <<<(N_NODES + 255) / 256, 256>>>();

    // 2. weight prep (transposed hi/lo splits) + x split
    k_prepW1<<<(256 * 256 + 255) / 256, 256>>>(W1);
    k_prepW2<<<(256 * 256 + 255) / 256, 256>>>(Wmu, Wls, bmu, bls);
    k_split <<<(n4 + 255) / 256, 256>>>(x, n4);

    // 3. XW = x @ W1 (tensor cores), fused agg1 self-loop init
    k_mma_gemm<<<gemm_grid, 256, SM_TOT>>>(pAh, pAl, pB1h, pB1l,
                                           N_NODES, 0, p_xw, p_agg1, nullptr);

    // 4. edge aggregation into agg1
    k_agg<<<(N_EDGES * 32) / 256, 256>>>(ei, 0);

    // 5. h = relu(agg1 + b1); agg2 init = h * dinv^2
    k_finalize<<<(n4 + 255) / 256, 256>>>(b1);

    // 6. edge aggregation of h into agg2
    k_agg<<<(N_EDGES * 32) / 256, 256>>>(ei, 1);

    // 7. split agg2, then fused [mu|logstd] GEMM straight into d_out
    k_split<<<(n4 + 255) / 256, 256>>>(p_agg2, n4);
    k_mma_gemm<<<gemm_grid, 256, SM_TOT>>>(pAh, pAl, pB2h, pB2l,
                                           N_NODES, 1, out, out + (size_t)N_NODES * OUT_CH,
                                           p_bcat);
}

// round 9
// speedup vs baseline: 2.2833x; 1.3184x over previous
#include <cuda_runtime.h>
#include <cuda_bf16.h>
#include <cstdint>

#define N_NODES 50000
#define N_EDGES 800000
#define IN_CH   256
#define HID_CH  256
#define OUT_CH  128

// ---------------- scratch (__device__ globals, no allocs) --------------------
__device__ float g_dinv[N_NODES];
__device__ int   g_degi[N_NODES];
__device__ int   g_off [N_NODES + 1];
__device__ int   g_cur [N_NODES];
__device__ int   g_esrc[N_EDGES];
__device__ float g_xw  [(size_t)N_NODES * HID_CH];
__device__ float g_h   [(size_t)N_NODES * HID_CH];
__device__ __nv_bfloat16 gA_hi[(size_t)N_NODES * IN_CH];
__device__ __nv_bfloat16 gA_lo[(size_t)N_NODES * IN_CH];
__device__ __nv_bfloat16 gB1_hi[IN_CH * HID_CH];   // W1^T  [n][k]
__device__ __nv_bfloat16 gB1_lo[IN_CH * HID_CH];
__device__ __nv_bfloat16 gB2_hi[HID_CH * HID_CH];  // [Wmu|Wls]^T [n][k]
__device__ __nv_bfloat16 gB2_lo[HID_CH * HID_CH];
__device__ float g_bcat[256];

// ---------------- helpers ----------------------------------------------------
__device__ __forceinline__ uint32_t smem_u32(const void* p) {
    uint32_t a;
    asm("{ .reg .u64 t; cvta.to.shared.u64 t, %1; cvt.u32.u64 %0, t; }" : "=r"(a) : "l"(p));
    return a;
}
__device__ __forceinline__ uint32_t sw128(uint32_t off) { return off ^ ((off >> 3) & 0x70); }

#define LDSM_X4(r, addr) \
    asm volatile("ldmatrix.sync.aligned.m8n8.x4.shared.b16 {%0,%1,%2,%3}, [%4];" \
                 : "=r"((r)[0]), "=r"((r)[1]), "=r"((r)[2]), "=r"((r)[3]) : "r"(addr))
#define LDSM_X2(r, addr) \
    asm volatile("ldmatrix.sync.aligned.m8n8.x2.shared.b16 {%0,%1}, [%2];" \
                 : "=r"((r)[0]), "=r"((r)[1]) : "r"(addr))

__device__ __forceinline__ void mma_bf16(float* c, const uint32_t* a, const uint32_t* b) {
    asm volatile(
        "mma.sync.aligned.m16n8k16.row.col.f32.bf16.bf16.f32 "
        "{%0,%1,%2,%3}, {%4,%5,%6,%7}, {%8,%9}, {%0,%1,%2,%3};"
        : "+f"(c[0]), "+f"(c[1]), "+f"(c[2]), "+f"(c[3])
        : "r"(a[0]), "r"(a[1]), "r"(a[2]), "r"(a[3]), "r"(b[0]), "r"(b[1]));
}

// ---------------- CSR build --------------------------------------------------
__global__ void k_zero() {
    int i = blockIdx.x * blockDim.x + threadIdx.x;
    if (i < N_NODES) g_degi[i] = 0;
}
__global__ void k_cnt(const int* __restrict__ ei) {
    int e = blockIdx.x * blockDim.x + threadIdx.x;
    if (e < N_EDGES) atomicAdd(&g_degi[ei[N_EDGES + e]], 1);
}
__global__ void k_dinv() {
    int i = blockIdx.x * blockDim.x + threadIdx.x;
    if (i < N_NODES) g_dinv[i] = rsqrtf(1.0f + (float)g_degi[i]);  // + self loop
}

#define SCAN_T 1024
__global__ void __launch_bounds__(SCAN_T) k_scan() {
    __shared__ int part[SCAN_T];
    const int tid = threadIdx.x;
    const int CH  = (N_NODES + SCAN_T - 1) / SCAN_T;   // 49
    const int base = tid * CH;
    int s = 0;
    for (int j = 0; j < CH; j++) {
        int i = base + j;
        if (i < N_NODES) { int t = g_degi[i]; g_off[i] = s; s += t; }
    }
    part[tid] = s;
    __syncthreads();
    for (int d = 1; d < SCAN_T; d <<= 1) {
        int v = (tid >= d) ? part[tid - d] : 0;
        __syncthreads();
        part[tid] += v;
        __syncthreads();
    }
    int pre = (tid == 0) ? 0 : part[tid - 1];
    for (int j = 0; j < CH; j++) {
        int i = base + j;
        if (i < N_NODES) { g_off[i] += pre; g_cur[i] = g_off[i]; }
    }
    if (tid == SCAN_T - 1) g_off[N_NODES] = part[SCAN_T - 1];
}

__global__ void k_scatter(const int* __restrict__ ei) {
    int e = blockIdx.x * blockDim.x + threadIdx.x;
    if (e >= N_EDGES) return;
    int src = ei[e];
    int dst = ei[N_EDGES + e];
    int pos = atomicAdd(&g_cur[dst], 1);
    g_esrc[pos] = src;
}

// ---------------- fp32 -> bf16 hi/lo split (Dekker) --------------------------
__global__ void k_split(const float* __restrict__ src, size_t n4) {
    size_t q = (size_t)blockIdx.x * blockDim.x + threadIdx.x;
    if (q >= n4) return;
    float4 v = reinterpret_cast<const float4*>(src)[q];
    __nv_bfloat16 hx = __float2bfloat16(v.x), hy = __float2bfloat16(v.y);
    __nv_bfloat16 hz = __float2bfloat16(v.z), hw = __float2bfloat16(v.w);
    __nv_bfloat162* H = reinterpret_cast<__nv_bfloat162*>(gA_hi);
    __nv_bfloat162* L = reinterpret_cast<__nv_bfloat162*>(gA_lo);
    H[q * 2 + 0] = __nv_bfloat162(hx, hy);
    H[q * 2 + 1] = __nv_bfloat162(hz, hw);
    L[q * 2 + 0] = __nv_bfloat162(__float2bfloat16(v.x - __bfloat162float(hx)),
                                  __float2bfloat16(v.y - __bfloat162float(hy)));
    L[q * 2 + 1] = __nv_bfloat162(__float2bfloat16(v.z - __bfloat162float(hz)),
                                  __float2bfloat16(v.w - __bfloat162float(hw)));
}

// W1 [K=256][N=256] -> gB1 [n][k] (transposed, split)
__global__ void k_prepW1(const float* __restrict__ W) {
    int idx = blockIdx.x * blockDim.x + threadIdx.x;
    if (idx >= 256 * 256) return;
    int n = idx >> 8, k = idx & 255;
    float v = W[k * 256 + n];
    __nv_bfloat16 h = __float2bfloat16(v);
    gB1_hi[idx] = h;
    gB1_lo[idx] = __float2bfloat16(v - __bfloat162float(h));
}

// [Wmu|Wls] (each [256][128]) -> gB2 [n][k]; also bias concat
__global__ void k_prepW2(const float* __restrict__ Wmu, const float* __restrict__ Wls,
                         const float* __restrict__ bmu, const float* __restrict__ bls) {
    int idx = blockIdx.x * blockDim.x + threadIdx.x;
    if (idx >= 256 * 256) return;
    int n = idx >> 8, k = idx & 255;
    float v = (n < 128) ? Wmu[k * 128 + n] : Wls[k * 128 + (n - 128)];
    __nv_bfloat16 h = __float2bfloat16(v);
    gB2_hi[idx] = h;
    gB2_lo[idx] = __float2bfloat16(v - __bfloat162float(h));
    if (k == 0) g_bcat[n] = (n < 128) ? bmu[n] : bls[n - 128];
}

// ---------------- mma.sync GEMM: C[M,256] = A[M,256] @ B^T --------------------
// CTA 128x128, BK=64, 8 warps (2x4), warp tile 64x32.  3 MMAs/k16 (Dekker).
// mode 0: out0 = raw (xw, stride 256).
// mode 1: column block 0 -> out0 (+bias), block 1 -> out1 (+bias), stride 128.
#define SM_AHI 0u
#define SM_ALO 16384u
#define SM_BHI 32768u
#define SM_BLO 49152u
#define SM_TOT 65536

__global__ void __launch_bounds__(256, 1)
k_mma_gemm(const __nv_bfloat16* __restrict__ Ahi, const __nv_bfloat16* __restrict__ Alo,
           const __nv_bfloat16* __restrict__ Bhi, const __nv_bfloat16* __restrict__ Blo,
           int M, int mode,
           float* __restrict__ out0, float* __restrict__ out1,
           const float* __restrict__ bias)
{
    extern __shared__ char smem[];
    const uint32_t sb = smem_u32(smem);
    const int tid = threadIdx.x, lane = tid & 31, wid = tid >> 5;
    const int wm = wid >> 2, wn = wid & 3;
    const int bm = blockIdx.y * 128, bn = blockIdx.x * 128;

    float acc[4][4][4];
#pragma unroll
    for (int f = 0; f < 4; f++)
#pragma unroll
        for (int g = 0; g < 4; g++)
#pragma unroll
            for (int r = 0; r < 4; r++) acc[f][g][r] = 0.0f;

    for (int ch = 0; ch < 4; ch++) {
        const int k0 = ch * 64;
#pragma unroll
        for (int i = 0; i < 4; i++) {
            int u = tid + i * 256;
            int row = u >> 3, j = u & 7;
            uint32_t dst = sw128(row * 128 + j * 16);
            uint4 vh = make_uint4(0, 0, 0, 0), vl = make_uint4(0, 0, 0, 0);
            if (bm + row < M) {
                vh = *reinterpret_cast<const uint4*>(Ahi + (size_t)(bm + row) * 256 + k0 + j * 8);
                vl = *reinterpret_cast<const uint4*>(Alo + (size_t)(bm + row) * 256 + k0 + j * 8);
            }
            *reinterpret_cast<uint4*>(smem + SM_AHI + dst) = vh;
            *reinterpret_cast<uint4*>(smem + SM_ALO + dst) = vl;
            *reinterpret_cast<uint4*>(smem + SM_BHI + dst) =
                *reinterpret_cast<const uint4*>(Bhi + (size_t)(bn + row) * 256 + k0 + j * 8);
            *reinterpret_cast<uint4*>(smem + SM_BLO + dst) =
                *reinterpret_cast<const uint4*>(Blo + (size_t)(bn + row) * 256 + k0 + j * 8);
        }
        __syncthreads();

#pragma unroll
        for (int s = 0; s < 4; s++) {
            uint32_t ah[4][4], al[4][4], bh[4][2], bl[4][2];
#pragma unroll
            for (int f = 0; f < 4; f++) {
                int row = wm * 64 + f * 16 + (lane & 15);
                int kb  = s * 32 + (lane >> 4) * 16;
                uint32_t ad = sw128((uint32_t)(row * 128 + kb));
                LDSM_X4(ah[f], sb + SM_AHI + ad);
                LDSM_X4(al[f], sb + SM_ALO + ad);
            }
#pragma unroll
            for (int g = 0; g < 4; g++) {
                int row = wn * 32 + g * 8 + (lane & 7);
                int kb  = s * 32 + ((lane >> 3) & 1) * 16;
                uint32_t ad = sw128((uint32_t)(row * 128 + kb));
                LDSM_X2(bh[g], sb + SM_BHI + ad);
                LDSM_X2(bl[g], sb + SM_BLO + ad);
            }
#pragma unroll
            for (int f = 0; f < 4; f++)
#pragma unroll
                for (int g = 0; g < 4; g++) {
                    mma_bf16(acc[f][g], ah[f], bh[g]);
                    mma_bf16(acc[f][g], al[f], bh[g]);
                    mma_bf16(acc[f][g], ah[f], bl[g]);
                }
        }
        __syncthreads();
    }

#pragma unroll
    for (int f = 0; f < 4; f++) {
        int r0 = bm + wm * 64 + f * 16 + (lane >> 2);
#pragma unroll
        for (int half = 0; half < 2; half++) {
            int gr = r0 + half * 8;
            if (gr >= M) continue;
#pragma unroll
            for (int g = 0; g < 4; g++) {
                int col = bn + wn * 32 + g * 8 + (lane & 3) * 2;
                float v0 = acc[f][g][half * 2 + 0];
                float v1 = acc[f][g][half * 2 + 1];
                if (mode == 0) {
                    *reinterpret_cast<float2*>(out0 + (size_t)gr * 256 + col) =
                        make_float2(v0, v1);
                } else {
                    float* base = (bn == 0) ? out0 : out1;
                    int cl = col - bn;
                    *reinterpret_cast<float2*>(base + (size_t)gr * 128 + cl) =
                        make_float2(v0 + bias[col], v1 + bias[col + 1]);
                }
            }
        }
    }
}

// ---------------- CSR gather aggregation (one warp per dst node) -------------
// pass 0: h[n] = relu( dinv^2 * xw[n] + sum nrm * xw[src] + b1 )
// pass 1: a = dinv^2 * h[n] + sum nrm * h[src]; write bf16 hi/lo split directly
__global__ void __launch_bounds__(256)
k_agg_csr(int pass, const float* __restrict__ b1)
{
    const int w    = (blockIdx.x * blockDim.x + threadIdx.x) >> 5;
    const int lane = threadIdx.x & 31;
    if (w >= N_NODES) return;

    const float* __restrict__ in = pass ? g_h : g_xw;
    const float dn = g_dinv[w];
    const float dd = dn * dn;

    const float4* selfrow = reinterpret_cast<const float4*>(in + (size_t)w * 256);
    float4 s0 = selfrow[lane];
    float4 s1 = selfrow[lane + 32];
    float4 a0 = make_float4(s0.x * dd, s0.y * dd, s0.z * dd, s0.w * dd);
    float4 a1 = make_float4(s1.x * dd, s1.y * dd, s1.z * dd, s1.w * dd);

    const int st = g_off[w];
    const int en = g_off[w + 1];
    for (int e = st; e < en; e++) {
        int s = g_esrc[e];
        float nrm = g_dinv[s] * dn;
        const float4* r = reinterpret_cast<const float4*>(in + (size_t)s * 256);
        float4 v0 = r[lane];
        float4 v1 = r[lane + 32];
        a0.x = fmaf(nrm, v0.x, a0.x); a0.y = fmaf(nrm, v0.y, a0.y);
        a0.z = fmaf(nrm, v0.z, a0.z); a0.w = fmaf(nrm, v0.w, a0.w);
        a1.x = fmaf(nrm, v1.x, a1.x); a1.y = fmaf(nrm, v1.y, a1.y);
        a1.z = fmaf(nrm, v1.z, a1.z); a1.w = fmaf(nrm, v1.w, a1.w);
    }

    if (pass == 0) {
        const float4* bb = reinterpret_cast<const float4*>(b1);
        float4 b0 = bb[lane], b1v = bb[lane + 32];
        a0.x = fmaxf(a0.x + b0.x, 0.f);  a0.y = fmaxf(a0.y + b0.y, 0.f);
        a0.z = fmaxf(a0.z + b0.z, 0.f);  a0.w = fmaxf(a0.w + b0.w, 0.f);
        a1.x = fmaxf(a1.x + b1v.x, 0.f); a1.y = fmaxf(a1.y + b1v.y, 0.f);
        a1.z = fmaxf(a1.z + b1v.z, 0.f); a1.w = fmaxf(a1.w + b1v.w, 0.f);
        float4* o = reinterpret_cast<float4*>(g_h + (size_t)w * 256);
        o[lane] = a0;
        o[lane + 32] = a1;
    } else {
        __nv_bfloat162 h0a(__float2bfloat16(a0.x), __float2bfloat16(a0.y));
        __nv_bfloat162 h0b(__float2bfloat16(a0.z), __float2bfloat16(a0.w));
        __nv_bfloat162 l0a(__float2bfloat16(a0.x - __bfloat162float(h0a.x)),
                           __float2bfloat16(a0.y - __bfloat162float(h0a.y)));
        __nv_bfloat162 l0b(__float2bfloat16(a0.z - __bfloat162float(h0b.x)),
                           __float2bfloat16(a0.w - __bfloat162float(h0b.y)));
        __nv_bfloat162 h1a(__float2bfloat16(a1.x), __float2bfloat16(a1.y));
        __nv_bfloat162 h1b(__float2bfloat16(a1.z), __float2bfloat16(a1.w));
        __nv_bfloat162 l1a(__float2bfloat16(a1.x - __bfloat162float(h1a.x)),
                           __float2bfloat16(a1.y - __bfloat162float(h1a.y)));
        __nv_bfloat162 l1b(__float2bfloat16(a1.z - __bfloat162float(h1b.x)),
                           __float2bfloat16(a1.w - __bfloat162float(h1b.y)));
        __nv_bfloat162* H = reinterpret_cast<__nv_bfloat162*>(gA_hi + (size_t)w * 256);
        __nv_bfloat162* L = reinterpret_cast<__nv_bfloat162*>(gA_lo + (size_t)w * 256);
        H[lane * 2 + 0] = h0a;  H[lane * 2 + 1] = h0b;
        H[64 + lane * 2 + 0] = h1a;  H[64 + lane * 2 + 1] = h1b;
        L[lane * 2 + 0] = l0a;  L[lane * 2 + 1] = l0b;
        L[64 + lane * 2 + 0] = l1a;  L[64 + lane * 2 + 1] = l1b;
    }
}

// ---------------- launch ----------------------------------------------------
extern "C" void kernel_launch(void* const* d_in, const int* in_sizes, int n_in,
                              void* d_out, int out_size)
{
    const float* x   = (const float*)d_in[0];
    const int*   ei  = (const int*)d_in[1];
    const float* W1  = (const float*)d_in[2];
    const float* b1  = (const float*)d_in[3];
    const float* Wmu = (const float*)d_in[4];
    const float* bmu = (const float*)d_in[5];
    const float* Wls = (const float*)d_in[6];
    const float* bls = (const float*)d_in[7];
    float*       out = (float*)d_out;

    float *p_xw, *p_bcat;
    __nv_bfloat16 *pAh, *pAl, *pB1h, *pB1l, *pB2h, *pB2l;
    cudaGetSymbolAddress((void**)&p_xw,   g_xw);
    cudaGetSymbolAddress((void**)&p_bcat, g_bcat);
    cudaGetSymbolAddress((void**)&pAh,  gA_hi);
    cudaGetSymbolAddress((void**)&pAl,  gA_lo);
    cudaGetSymbolAddress((void**)&pB1h, gB1_hi);
    cudaGetSymbolAddress((void**)&pB1l, gB1_lo);
    cudaGetSymbolAddress((void**)&pB2h, gB2_hi);
    cudaGetSymbolAddress((void**)&pB2l, gB2_lo);

    cudaFuncSetAttribute(k_mma_gemm, cudaFuncAttributeMaxDynamicSharedMemorySize, SM_TOT);

    const size_t n4 = (size_t)N_NODES * HID_CH / 4;
    dim3 gemm_grid(2, (N_NODES + 127) / 128);

    // 1. CSR build + normalization
    k_zero   <<<(N_NODES + 255) / 256, 256>>>();
    k_cnt    <<<(N_EDGES + 255) / 256, 256>>>(ei);
    k_dinv   <<<(N_NODES + 255) / 256, 256>>>();
    k_scan   <<<1, SCAN_T>>>();
    k_scatter<<<(N_EDGES + 255) / 256, 256>>>(ei);

    // 2. weight prep + x split
    k_prepW1<<<(256 * 256 + 255) / 256, 256>>>(W1);
    k_prepW2<<<(256 * 256 + 255) / 256, 256>>>(Wmu, Wls, bmu, bls);
    k_split <<<(n4 + 255) / 256, 256>>>(x, n4);

    // 3. XW = x @ W1 (tensor cores)
    k_mma_gemm<<<gemm_grid, 256, SM_TOT>>>(pAh, pAl, pB1h, pB1l,
                                           N_NODES, 0, p_xw, nullptr, nullptr);

    // 4. CSR agg pass 1: h = relu(agg(xw) + b1)   (fused bias/relu/self-loop)
    k_agg_csr<<<(N_NODES * 32 + 255) / 256, 256>>>(0, b1);

    // 5. CSR agg pass 2: agg(h), written directly as bf16 hi/lo split
    k_agg_csr<<<(N_NODES * 32 + 255) / 256, 256>>>(1, nullptr);

    // 6. fused [mu|logstd] GEMM straight into d_out
    k_mma_gemm<<<gemm_grid, 256, SM_TOT>>>(pAh, pAl, pB2h, pB2l,
                                           N_NODES, 1, out, out + (size_t)N_NODES * OUT_CH,
                                           p_bcat);
}

// round 13
// speedup vs baseline: 2.9212x; 1.2794x over previous
#include <cuda_runtime.h>
#include <cuda_bf16.h>
#include <cstdint>

#define N_NODES 50000
#define N_EDGES 800000
#define IN_CH   256
#define HID_CH  256
#define OUT_CH  128

// ---------------- scratch (__device__ globals, no allocs) --------------------
__device__ float g_dinv[N_NODES];
__device__ int   g_degi[N_NODES];
__device__ int   g_off [N_NODES + 1];
__device__ int   g_cur [N_NODES];
__device__ int   g_total;
__device__ int   g_esrc[N_EDGES];
__device__ float g_xw  [(size_t)N_NODES * HID_CH];
__device__ float g_h   [(size_t)N_NODES * HID_CH];
__device__ __nv_bfloat16 gA_hi[(size_t)N_NODES * IN_CH];
__device__ __nv_bfloat16 gA_lo[(size_t)N_NODES * IN_CH];
__device__ __nv_bfloat16 gB1_hi[IN_CH * HID_CH];   // W1^T  [n][k]
__device__ __nv_bfloat16 gB1_lo[IN_CH * HID_CH];
__device__ __nv_bfloat16 gB2_hi[HID_CH * HID_CH];  // [Wmu|Wls]^T [n][k]
__device__ __nv_bfloat16 gB2_lo[HID_CH * HID_CH];
__device__ float g_bcat[256];

// ---------------- helpers ----------------------------------------------------
__device__ __forceinline__ uint32_t smem_u32(const void* p) {
    uint32_t a;
    asm("{ .reg .u64 t; cvta.to.shared.u64 t, %1; cvt.u32.u64 %0, t; }" : "=r"(a) : "l"(p));
    return a;
}
__device__ __forceinline__ uint32_t sw128(uint32_t off) { return off ^ ((off >> 3) & 0x70); }

#define LDSM_X4(r, addr) \
    asm volatile("ldmatrix.sync.aligned.m8n8.x4.shared.b16 {%0,%1,%2,%3}, [%4];" \
                 : "=r"((r)[0]), "=r"((r)[1]), "=r"((r)[2]), "=r"((r)[3]) : "r"(addr))
#define LDSM_X2(r, addr) \
    asm volatile("ldmatrix.sync.aligned.m8n8.x2.shared.b16 {%0,%1}, [%2];" \
                 : "=r"((r)[0]), "=r"((r)[1]) : "r"(addr))

__device__ __forceinline__ void mma_bf16(float* c, const uint32_t* a, const uint32_t* b) {
    asm volatile(
        "mma.sync.aligned.m16n8k16.row.col.f32.bf16.bf16.f32 "
        "{%0,%1,%2,%3}, {%4,%5,%6,%7}, {%8,%9}, {%0,%1,%2,%3};"
        : "+f"(c[0]), "+f"(c[1]), "+f"(c[2]), "+f"(c[3])
        : "r"(a[0]), "r"(a[1]), "r"(a[2]), "r"(a[3]), "r"(b[0]), "r"(b[1]));
}

// ---------------- CSR build --------------------------------------------------
__global__ void k_zero() {
    int i = blockIdx.x * blockDim.x + threadIdx.x;
    if (i < N_NODES) g_degi[i] = 0;
    if (i == 0) g_total = 0;
}
__global__ void k_cnt(const int* __restrict__ ei) {
    int e = blockIdx.x * blockDim.x + threadIdx.x;
    if (e < N_EDGES) atomicAdd(&g_degi[ei[N_EDGES + e]], 1);
}

// Decoupled block scan: ranges need only be DISJOINT, not node-ordered,
// so each block grabs its base with one atomicAdd on a global counter.
// Also computes dinv (pure function of degi) in the same pass.
__global__ void __launch_bounds__(256) k_offsets() {
    __shared__ int wsum[8];
    __shared__ int sbase;
    const int i    = blockIdx.x * 256 + threadIdx.x;
    const int lane = threadIdx.x & 31;
    const int wid  = threadIdx.x >> 5;

    int d = (i < N_NODES) ? g_degi[i] : 0;
    if (i < N_NODES) g_dinv[i] = rsqrtf(1.0f + (float)d);   // + self loop
    int v = d;
#pragma unroll
    for (int o = 1; o < 32; o <<= 1) {
        int t = __shfl_up_sync(0xFFFFFFFFu, v, o);
        if (lane >= o) v += t;
    }
    if (lane == 31) wsum[wid] = v;
    __syncthreads();
    if (wid == 0) {
        int w = (lane < 8) ? wsum[lane] : 0;
#pragma unroll
        for (int o = 1; o < 8; o <<= 1) {
            int t = __shfl_up_sync(0xFFFFFFFFu, w, o);
            if (lane >= o) w += t;
        }
        if (lane < 8) wsum[lane] = w;
        if (lane == 7) sbase = atomicAdd(&g_total, w);
    }
    __syncthreads();
    int base = sbase + (wid ? wsum[wid - 1] : 0);
    int excl = base + v - d;
    if (i < N_NODES) { g_off[i] = excl; g_cur[i] = excl; }
}

__global__ void k_scatter(const int* __restrict__ ei) {
    int e = blockIdx.x * blockDim.x + threadIdx.x;
    if (e >= N_EDGES) return;
    int src = ei[e];
    int dst = ei[N_EDGES + e];
    int pos = atomicAdd(&g_cur[dst], 1);
    g_esrc[pos] = src;
}

// ---------------- fp32 -> bf16 hi/lo split (Dekker) --------------------------
__global__ void k_split(const float* __restrict__ src, size_t n4) {
    size_t q = (size_t)blockIdx.x * blockDim.x + threadIdx.x;
    if (q >= n4) return;
    float4 v = reinterpret_cast<const float4*>(src)[q];
    __nv_bfloat16 hx = __float2bfloat16(v.x), hy = __float2bfloat16(v.y);
    __nv_bfloat16 hz = __float2bfloat16(v.z), hw = __float2bfloat16(v.w);
    __nv_bfloat162* H = reinterpret_cast<__nv_bfloat162*>(gA_hi);
    __nv_bfloat162* L = reinterpret_cast<__nv_bfloat162*>(gA_lo);
    H[q * 2 + 0] = __nv_bfloat162(hx, hy);
    H[q * 2 + 1] = __nv_bfloat162(hz, hw);
    L[q * 2 + 0] = __nv_bfloat162(__float2bfloat16(v.x - __bfloat162float(hx)),
                                  __float2bfloat16(v.y - __bfloat162float(hy)));
    L[q * 2 + 1] = __nv_bfloat162(__float2bfloat16(v.z - __bfloat162float(hz)),
                                  __float2bfloat16(v.w - __bfloat162float(hw)));
}

// W1 [K=256][N=256] -> gB1 [n][k] (transposed, split)
__global__ void k_prepW1(const float* __restrict__ W) {
    int idx = blockIdx.x * blockDim.x + threadIdx.x;
    if (idx >= 256 * 256) return;
    int n = idx >> 8, k = idx & 255;
    float v = W[k * 256 + n];
    __nv_bfloat16 h = __float2bfloat16(v);
    gB1_hi[idx] = h;
    gB1_lo[idx] = __float2bfloat16(v - __bfloat162float(h));
}

// [Wmu|Wls] (each [256][128]) -> gB2 [n][k]; also bias concat
__global__ void k_prepW2(const float* __restrict__ Wmu, const float* __restrict__ Wls,
                         const float* __restrict__ bmu, const float* __restrict__ bls) {
    int idx = blockIdx.x * blockDim.x + threadIdx.x;
    if (idx >= 256 * 256) return;
    int n = idx >> 8, k = idx & 255;
    float v = (n < 128) ? Wmu[k * 128 + n] : Wls[k * 128 + (n - 128)];
    __nv_bfloat16 h = __float2bfloat16(v);
    gB2_hi[idx] = h;
    gB2_lo[idx] = __float2bfloat16(v - __bfloat162float(h));
    if (k == 0) g_bcat[n] = (n < 128) ? bmu[n] : bls[n - 128];
}

// ---------------- mma.sync GEMM: C[M,256] = A[M,256] @ B^T --------------------
// CTA 128x128, BK=64, 8 warps (2x4), warp tile 64x32.  3 MMAs/k16 (Dekker).
// mode 0: out0 = raw (xw, stride 256).
// mode 1: column block 0 -> out0 (+bias), block 1 -> out1 (+bias), stride 128.
#define SM_AHI 0u
#define SM_ALO 16384u
#define SM_BHI 32768u
#define SM_BLO 49152u
#define SM_TOT 65536

__global__ void __launch_bounds__(256, 1)
k_mma_gemm(const __nv_bfloat16* __restrict__ Ahi, const __nv_bfloat16* __restrict__ Alo,
           const __nv_bfloat16* __restrict__ Bhi, const __nv_bfloat16* __restrict__ Blo,
           int M, int mode,
           float* __restrict__ out0, float* __restrict__ out1,
           const float* __restrict__ bias)
{
    extern __shared__ char smem[];
    const uint32_t sb = smem_u32(smem);
    const int tid = threadIdx.x, lane = tid & 31, wid = tid >> 5;
    const int wm = wid >> 2, wn = wid & 3;
    const int bm = blockIdx.y * 128, bn = blockIdx.x * 128;

    float acc[4][4][4];
#pragma unroll
    for (int f = 0; f < 4; f++)
#pragma unroll
        for (int g = 0; g < 4; g++)
#pragma unroll
            for (int r = 0; r < 4; r++) acc[f][g][r] = 0.0f;

    for (int ch = 0; ch < 4; ch++) {
        const int k0 = ch * 64;
#pragma unroll
        for (int i = 0; i < 4; i++) {
            int u = tid + i * 256;
            int row = u >> 3, j = u & 7;
            uint32_t dst = sw128(row * 128 + j * 16);
            uint4 vh = make_uint4(0, 0, 0, 0), vl = make_uint4(0, 0, 0, 0);
            if (bm + row < M) {
                vh = *reinterpret_cast<const uint4*>(Ahi + (size_t)(bm + row) * 256 + k0 + j * 8);
                vl = *reinterpret_cast<const uint4*>(Alo + (size_t)(bm + row) * 256 + k0 + j * 8);
            }
            *reinterpret_cast<uint4*>(smem + SM_AHI + dst) = vh;
            *reinterpret_cast<uint4*>(smem + SM_ALO + dst) = vl;
            *reinterpret_cast<uint4*>(smem + SM_BHI + dst) =
                *reinterpret_cast<const uint4*>(Bhi + (size_t)(bn + row) * 256 + k0 + j * 8);
            *reinterpret_cast<uint4*>(smem + SM_BLO + dst) =
                *reinterpret_cast<const uint4*>(Blo + (size_t)(bn + row) * 256 + k0 + j * 8);
        }
        __syncthreads();

#pragma unroll
        for (int s = 0; s < 4; s++) {
            uint32_t ah[4][4], al[4][4], bh[4][2], bl[4][2];
#pragma unroll
            for (int f = 0; f < 4; f++) {
                int row = wm * 64 + f * 16 + (lane & 15);
                int kb  = s * 32 + (lane >> 4) * 16;
                uint32_t ad = sw128((uint32_t)(row * 128 + kb));
                LDSM_X4(ah[f], sb + SM_AHI + ad);
                LDSM_X4(al[f], sb + SM_ALO + ad);
            }
#pragma unroll
            for (int g = 0; g < 4; g++) {
                int row = wn * 32 + g * 8 + (lane & 7);
                int kb  = s * 32 + ((lane >> 3) & 1) * 16;
                uint32_t ad = sw128((uint32_t)(row * 128 + kb));
                LDSM_X2(bh[g], sb + SM_BHI + ad);
                LDSM_X2(bl[g], sb + SM_BLO + ad);
            }
#pragma unroll
            for (int f = 0; f < 4; f++)
#pragma unroll
                for (int g = 0; g < 4; g++) {
                    mma_bf16(acc[f][g], ah[f], bh[g]);
                    mma_bf16(acc[f][g], al[f], bh[g]);
                    mma_bf16(acc[f][g], ah[f], bl[g]);
                }
        }
        __syncthreads();
    }

#pragma unroll
    for (int f = 0; f < 4; f++) {
        int r0 = bm + wm * 64 + f * 16 + (lane >> 2);
#pragma unroll
        for (int half = 0; half < 2; half++) {
            int gr = r0 + half * 8;
            if (gr >= M) continue;
#pragma unroll
            for (int g = 0; g < 4; g++) {
                int col = bn + wn * 32 + g * 8 + (lane & 3) * 2;
                float v0 = acc[f][g][half * 2 + 0];
                float v1 = acc[f][g][half * 2 + 1];
                if (mode == 0) {
                    *reinterpret_cast<float2*>(out0 + (size_t)gr * 256 + col) =
                        make_float2(v0, v1);
                } else {
                    float* base = (bn == 0) ? out0 : out1;
                    int cl = col - bn;
                    *reinterpret_cast<float2*>(base + (size_t)gr * 128 + cl) =
                        make_float2(v0 + bias[col], v1 + bias[col + 1]);
                }
            }
        }
    }
}

// ---------------- CSR gather aggregation (one warp per dst node) -------------
// pass 0: h[n] = relu( dinv^2 * xw[n] + sum nrm * xw[src] + b1 )
// pass 1: a = dinv^2 * h[n] + sum nrm * h[src]; write bf16 hi/lo split directly
__global__ void __launch_bounds__(256)
k_agg_csr(int pass, const float* __restrict__ b1)
{
    const int w    = (blockIdx.x * blockDim.x + threadIdx.x) >> 5;
    const int lane = threadIdx.x & 31;
    if (w >= N_NODES) return;

    const float* __restrict__ in = pass ? g_h : g_xw;
    const float dn = g_dinv[w];
    const float dd = dn * dn;

    const float4* selfrow = reinterpret_cast<const float4*>(in + (size_t)w * 256);
    float4 s0 = selfrow[lane];
    float4 s1 = selfrow[lane + 32];
    float4 a0 = make_float4(s0.x * dd, s0.y * dd, s0.z * dd, s0.w * dd);
    float4 a1 = make_float4(s1.x * dd, s1.y * dd, s1.z * dd, s1.w * dd);

    const int st = g_off[w];
    const int en = st + g_degi[w];       // ranges disjoint, not node-ordered
    int s_next = (st < en) ? g_esrc[st] : 0;
    for (int e = st; e < en; e++) {
        int s = s_next;
        if (e + 1 < en) s_next = g_esrc[e + 1];   // prefetch next index
        float nrm = g_dinv[s] * dn;
        const float4* r = reinterpret_cast<const float4*>(in + (size_t)s * 256);
        float4 v0 = r[lane];
        float4 v1 = r[lane + 32];
        a0.x = fmaf(nrm, v0.x, a0.x); a0.y = fmaf(nrm, v0.y, a0.y);
        a0.z = fmaf(nrm, v0.z, a0.z); a0.w = fmaf(nrm, v0.w, a0.w);
        a1.x = fmaf(nrm, v1.x, a1.x); a1.y = fmaf(nrm, v1.y, a1.y);
        a1.z = fmaf(nrm, v1.z, a1.z); a1.w = fmaf(nrm, v1.w, a1.w);
    }

    if (pass == 0) {
        const float4* bb = reinterpret_cast<const float4*>(b1);
        float4 b0 = bb[lane], b1v = bb[lane + 32];
        a0.x = fmaxf(a0.x + b0.x, 0.f);  a0.y = fmaxf(a0.y + b0.y, 0.f);
        a0.z = fmaxf(a0.z + b0.z, 0.f);  a0.w = fmaxf(a0.w + b0.w, 0.f);
        a1.x = fmaxf(a1.x + b1v.x, 0.f); a1.y = fmaxf(a1.y + b1v.y, 0.f);
        a1.z = fmaxf(a1.z + b1v.z, 0.f); a1.w = fmaxf(a1.w + b1v.w, 0.f);
        float4* o = reinterpret_cast<float4*>(g_h + (size_t)w * 256);
        o[lane] = a0;
        o[lane + 32] = a1;
    } else {
        __nv_bfloat162 h0a(__float2bfloat16(a0.x), __float2bfloat16(a0.y));
        __nv_bfloat162 h0b(__float2bfloat16(a0.z), __float2bfloat16(a0.w));
        __nv_bfloat162 l0a(__float2bfloat16(a0.x - __bfloat162float(h0a.x)),
                           __float2bfloat16(a0.y - __bfloat162float(h0a.y)));
        __nv_bfloat162 l0b(__float2bfloat16(a0.z - __bfloat162float(h0b.x)),
                           __float2bfloat16(a0.w - __bfloat162float(h0b.y)));
        __nv_bfloat162 h1a(__float2bfloat16(a1.x), __float2bfloat16(a1.y));
        __nv_bfloat162 h1b(__float2bfloat16(a1.z), __float2bfloat16(a1.w));
        __nv_bfloat162 l1a(__float2bfloat16(a1.x - __bfloat162float(h1a.x)),
                           __float2bfloat16(a1.y - __bfloat162float(h1a.y)));
        __nv_bfloat162 l1b(__float2bfloat16(a1.z - __bfloat162float(h1b.x)),
                           __float2bfloat16(a1.w - __bfloat162float(h1b.y)));
        __nv_bfloat162* H = reinterpret_cast<__nv_bfloat162*>(gA_hi + (size_t)w * 256);
        __nv_bfloat162* L = reinterpret_cast<__nv_bfloat162*>(gA_lo + (size_t)w * 256);
        H[lane * 2 + 0] = h0a;  H[lane * 2 + 1] = h0b;
        H[64 + lane * 2 + 0] = h1a;  H[64 + lane * 2 + 1] = h1b;
        L[lane * 2 + 0] = l0a;  L[lane * 2 + 1] = l0b;
        L[64 + lane * 2 + 0] = l1a;  L[64 + lane * 2 + 1] = l1b;
    }
}

// ---------------- launch ----------------------------------------------------
extern "C" void kernel_launch(void* const* d_in, const int* in_sizes, int n_in,
                              void* d_out, int out_size)
{
    const float* x   = (const float*)d_in[0];
    const int*   ei  = (const int*)d_in[1];
    const float* W1  = (const float*)d_in[2];
    const float* b1  = (const float*)d_in[3];
    const float* Wmu = (const float*)d_in[4];
    const float* bmu = (const float*)d_in[5];
    const float* Wls = (const float*)d_in[6];
    const float* bls = (const float*)d_in[7];
    float*       out = (float*)d_out;

    float *p_xw, *p_bcat;
    __nv_bfloat16 *pAh, *pAl, *pB1h, *pB1l, *pB2h, *pB2l;
    cudaGetSymbolAddress((void**)&p_xw,   g_xw);
    cudaGetSymbolAddress((void**)&p_bcat, g_bcat);
    cudaGetSymbolAddress((void**)&pAh,  gA_hi);
    cudaGetSymbolAddress((void**)&pAl,  gA_lo);
    cudaGetSymbolAddress((void**)&pB1h, gB1_hi);
    cudaGetSymbolAddress((void**)&pB1l, gB1_lo);
    cudaGetSymbolAddress((void**)&pB2h, gB2_hi);
    cudaGetSymbolAddress((void**)&pB2l, gB2_lo);

    cudaFuncSetAttribute(k_mma_gemm, cudaFuncAttributeMaxDynamicSharedMemorySize, SM_TOT);

    const size_t n4 = (size_t)N_NODES * HID_CH / 4;
    dim3 gemm_grid(2, (N_NODES + 127) / 128);

    // 1. CSR build + normalization (decoupled block scan; dinv fused in)
    k_zero   <<<(N_NODES + 255) / 256, 256>>>();
    k_cnt    <<<(N_EDGES + 255) / 256, 256>>>(ei);
    k_offsets<<<(N_NODES + 255) / 256, 256>>>();
    k_scatter<<<(N_EDGES + 255) / 256, 256>>>(ei);

    // 2. weight prep + x split
    k_prepW1<<<(256 * 256 + 255) / 256, 256>>>(W1);
    k_prepW2<<<(256 * 256 + 255) / 256, 256>>>(Wmu, Wls, bmu, bls);
    k_split <<<(n4 + 255) / 256, 256>>>(x, n4);

    // 3. XW = x @ W1 (tensor cores)
    k_mma_gemm<<<gemm_grid, 256, SM_TOT>>>(pAh, pAl, pB1h, pB1l,
                                           N_NODES, 0, p_xw, nullptr, nullptr);

    // 4. CSR agg pass 1: h = relu(agg(xw) + b1)   (fused bias/relu/self-loop)
    k_agg_csr<<<(N_NODES * 32 + 255) / 256, 256>>>(0, b1);

    // 5. CSR agg pass 2: agg(h), written directly as bf16 hi/lo split
    k_agg_csr<<<(N_NODES * 32 + 255) / 256, 256>>>(1, nullptr);

    // 6. fused [mu|logstd] GEMM straight into d_out
    k_mma_gemm<<<gemm_grid, 256, SM_TOT>>>(pAh, pAl, pB2h, pB2l,
                                           N_NODES, 1, out, out + (size_t)N_NODES * OUT_CH,
                                           p_bcat);
}

// round 16
// speedup vs baseline: 2.9898x; 1.0235x over previous
#include <cuda_runtime.h>
#include <cuda_bf16.h>
#include <cstdint>

#define N_NODES 50000
#define N_EDGES 800000
#define IN_CH   256
#define HID_CH  256
#define OUT_CH  128

// ---------------- scratch (__device__ globals, no allocs) --------------------
__device__ float g_dinv[N_NODES];
__device__ int   g_degi[N_NODES];
__device__ int   g_off [N_NODES + 1];
__device__ int   g_cur [N_NODES];
__device__ int   g_total;
__device__ int   g_esrc[N_EDGES];
__device__ float g_xw  [(size_t)N_NODES * HID_CH];
__device__ float g_h   [(size_t)N_NODES * HID_CH];
__device__ __nv_bfloat16 gA_hi[(size_t)N_NODES * IN_CH];
__device__ __nv_bfloat16 gA_lo[(size_t)N_NODES * IN_CH];
__device__ __nv_bfloat16 gB1_hi[IN_CH * HID_CH];   // W1^T  [n][k]
__device__ __nv_bfloat16 gB1_lo[IN_CH * HID_CH];
__device__ __nv_bfloat16 gB2_hi[HID_CH * HID_CH];  // [Wmu|Wls]^T [n][k]
__device__ __nv_bfloat16 gB2_lo[HID_CH * HID_CH];
__device__ float g_bcat[256];

// ---------------- helpers ----------------------------------------------------
__device__ __forceinline__ uint32_t smem_u32(const void* p) {
    uint32_t a;
    asm("{ .reg .u64 t; cvta.to.shared.u64 t, %1; cvt.u32.u64 %0, t; }" : "=r"(a) : "l"(p));
    return a;
}
__device__ __forceinline__ uint32_t sw128(uint32_t off) { return off ^ ((off >> 3) & 0x70); }

#define LDSM_X4(r, addr) \
    asm volatile("ldmatrix.sync.aligned.m8n8.x4.shared.b16 {%0,%1,%2,%3}, [%4];" \
                 : "=r"((r)[0]), "=r"((r)[1]), "=r"((r)[2]), "=r"((r)[3]) : "r"(addr))
#define LDSM_X2(r, addr) \
    asm volatile("ldmatrix.sync.aligned.m8n8.x2.shared.b16 {%0,%1}, [%2];" \
                 : "=r"((r)[0]), "=r"((r)[1]) : "r"(addr))

__device__ __forceinline__ void mma_bf16(float* c, const uint32_t* a, const uint32_t* b) {
    asm volatile(
        "mma.sync.aligned.m16n8k16.row.col.f32.bf16.bf16.f32 "
        "{%0,%1,%2,%3}, {%4,%5,%6,%7}, {%8,%9}, {%0,%1,%2,%3};"
        : "+f"(c[0]), "+f"(c[1]), "+f"(c[2]), "+f"(c[3])
        : "r"(a[0]), "r"(a[1]), "r"(a[2]), "r"(a[3]), "r"(b[0]), "r"(b[1]));
}

// ---------------- CSR build --------------------------------------------------
__global__ void k_zero() {
    int i = blockIdx.x * blockDim.x + threadIdx.x;
    if (i < N_NODES) g_degi[i] = 0;
    if (i == 0) g_total = 0;
}
__global__ void k_cnt(const int* __restrict__ ei) {
    int e = blockIdx.x * blockDim.x + threadIdx.x;
    if (e < N_EDGES) atomicAdd(&g_degi[ei[N_EDGES + e]], 1);
}

// Decoupled block scan: ranges need only be DISJOINT, not node-ordered,
// so each block grabs its base with one atomicAdd on a global counter.
// Also computes dinv (pure function of degi) in the same pass.
__global__ void __launch_bounds__(256) k_offsets() {
    __shared__ int wsum[8];
    __shared__ int sbase;
    const int i    = blockIdx.x * 256 + threadIdx.x;
    const int lane = threadIdx.x & 31;
    const int wid  = threadIdx.x >> 5;

    int d = (i < N_NODES) ? g_degi[i] : 0;
    if (i < N_NODES) g_dinv[i] = rsqrtf(1.0f + (float)d);   // + self loop
    int v = d;
#pragma unroll
    for (int o = 1; o < 32; o <<= 1) {
        int t = __shfl_up_sync(0xFFFFFFFFu, v, o);
        if (lane >= o) v += t;
    }
    if (lane == 31) wsum[wid] = v;
    __syncthreads();
    if (wid == 0) {
        int w = (lane < 8) ? wsum[lane] : 0;
#pragma unroll
        for (int o = 1; o < 8; o <<= 1) {
            int t = __shfl_up_sync(0xFFFFFFFFu, w, o);
            if (lane >= o) w += t;
        }
        if (lane < 8) wsum[lane] = w;
        if (lane == 7) sbase = atomicAdd(&g_total, w);
    }
    __syncthreads();
    int base = sbase + (wid ? wsum[wid - 1] : 0);
    int excl = base + v - d;
    if (i < N_NODES) { g_off[i] = excl; g_cur[i] = excl; }
}

__global__ void k_scatter(const int* __restrict__ ei) {
    int e = blockIdx.x * blockDim.x + threadIdx.x;
    if (e >= N_EDGES) return;
    int src = ei[e];
    int dst = ei[N_EDGES + e];
    int pos = atomicAdd(&g_cur[dst], 1);
    g_esrc[pos] = src;
}

// ---------------- fp32 -> bf16 hi/lo split (Dekker) --------------------------
__global__ void k_split(const float* __restrict__ src, size_t n4) {
    size_t q = (size_t)blockIdx.x * blockDim.x + threadIdx.x;
    if (q >= n4) return;
    float4 v = reinterpret_cast<const float4*>(src)[q];
    __nv_bfloat16 hx = __float2bfloat16(v.x), hy = __float2bfloat16(v.y);
    __nv_bfloat16 hz = __float2bfloat16(v.z), hw = __float2bfloat16(v.w);
    __nv_bfloat162* H = reinterpret_cast<__nv_bfloat162*>(gA_hi);
    __nv_bfloat162* L = reinterpret_cast<__nv_bfloat162*>(gA_lo);
    H[q * 2 + 0] = __nv_bfloat162(hx, hy);
    H[q * 2 + 1] = __nv_bfloat162(hz, hw);
    L[q * 2 + 0] = __nv_bfloat162(__float2bfloat16(v.x - __bfloat162float(hx)),
                                  __float2bfloat16(v.y - __bfloat162float(hy)));
    L[q * 2 + 1] = __nv_bfloat162(__float2bfloat16(v.z - __bfloat162float(hz)),
                                  __float2bfloat16(v.w - __bfloat162float(hw)));
}

// Merged weight prep: idx < 65536 -> W1^T split; else -> [Wmu|Wls]^T split.
__global__ void k_prepW(const float* __restrict__ W1,
                        const float* __restrict__ Wmu, const float* __restrict__ Wls,
                        const float* __restrict__ bmu, const float* __restrict__ bls) {
    int idx = blockIdx.x * blockDim.x + threadIdx.x;
    if (idx < 256 * 256) {
        int n = idx >> 8, k = idx & 255;
        float v = W1[k * 256 + n];
        __nv_bfloat16 h = __float2bfloat16(v);
        gB1_hi[idx] = h;
        gB1_lo[idx] = __float2bfloat16(v - __bfloat162float(h));
    } else if (idx < 2 * 256 * 256) {
        int j = idx - 256 * 256;
        int n = j >> 8, k = j & 255;
        float v = (n < 128) ? Wmu[k * 128 + n] : Wls[k * 128 + (n - 128)];
        __nv_bfloat16 h = __float2bfloat16(v);
        gB2_hi[j] = h;
        gB2_lo[j] = __float2bfloat16(v - __bfloat162float(h));
        if (k == 0) g_bcat[n] = (n < 128) ? bmu[n] : bls[n - 128];
    }
}

// ---------------- mma.sync GEMM: C[M,256] = A[M,256] @ B^T --------------------
// CTA 128x128, BK=64, 8 warps (2x4), warp tile 64x32.  3 MMAs/k16 (Dekker).
// mode 0: out0 = raw (xw, stride 256).
// mode 1: column block 0 -> out0 (+bias), block 1 -> out1 (+bias), stride 128.
#define SM_AHI 0u
#define SM_ALO 16384u
#define SM_BHI 32768u
#define SM_BLO 49152u
#define SM_TOT 65536

__global__ void __launch_bounds__(256, 1)
k_mma_gemm(const __nv_bfloat16* __restrict__ Ahi, const __nv_bfloat16* __restrict__ Alo,
           const __nv_bfloat16* __restrict__ Bhi, const __nv_bfloat16* __restrict__ Blo,
           int M, int mode,
           float* __restrict__ out0, float* __restrict__ out1,
           const float* __restrict__ bias)
{
    extern __shared__ char smem[];
    const uint32_t sb = smem_u32(smem);
    const int tid = threadIdx.x, lane = tid & 31, wid = tid >> 5;
    const int wm = wid >> 2, wn = wid & 3;
    const int bm = blockIdx.y * 128, bn = blockIdx.x * 128;

    float acc[4][4][4];
#pragma unroll
    for (int f = 0; f < 4; f++)
#pragma unroll
        for (int g = 0; g < 4; g++)
#pragma unroll
            for (int r = 0; r < 4; r++) acc[f][g][r] = 0.0f;

    for (int ch = 0; ch < 4; ch++) {
        const int k0 = ch * 64;
#pragma unroll
        for (int i = 0; i < 4; i++) {
            int u = tid + i * 256;
            int row = u >> 3, j = u & 7;
            uint32_t dst = sw128(row * 128 + j * 16);
            uint4 vh = make_uint4(0, 0, 0, 0), vl = make_uint4(0, 0, 0, 0);
            if (bm + row < M) {
                vh = *reinterpret_cast<const uint4*>(Ahi + (size_t)(bm + row) * 256 + k0 + j * 8);
                vl = *reinterpret_cast<const uint4*>(Alo + (size_t)(bm + row) * 256 + k0 + j * 8);
            }
            *reinterpret_cast<uint4*>(smem + SM_AHI + dst) = vh;
            *reinterpret_cast<uint4*>(smem + SM_ALO + dst) = vl;
            *reinterpret_cast<uint4*>(smem + SM_BHI + dst) =
                *reinterpret_cast<const uint4*>(Bhi + (size_t)(bn + row) * 256 + k0 + j * 8);
            *reinterpret_cast<uint4*>(smem + SM_BLO + dst) =
                *reinterpret_cast<const uint4*>(Blo + (size_t)(bn + row) * 256 + k0 + j * 8);
        }
        __syncthreads();

#pragma unroll
        for (int s = 0; s < 4; s++) {
            uint32_t ah[4][4], al[4][4], bh[4][2], bl[4][2];
#pragma unroll
            for (int f = 0; f < 4; f++) {
                int row = wm * 64 + f * 16 + (lane & 15);
                int kb  = s * 32 + (lane >> 4) * 16;
                uint32_t ad = sw128((uint32_t)(row * 128 + kb));
                LDSM_X4(ah[f], sb + SM_AHI + ad);
                LDSM_X4(al[f], sb + SM_ALO + ad);
            }
#pragma unroll
            for (int g = 0; g < 4; g++) {
                int row = wn * 32 + g * 8 + (lane & 7);
                int kb  = s * 32 + ((lane >> 3) & 1) * 16;
                uint32_t ad = sw128((uint32_t)(row * 128 + kb));
                LDSM_X2(bh[g], sb + SM_BHI + ad);
                LDSM_X2(bl[g], sb + SM_BLO + ad);
            }
#pragma unroll
            for (int f = 0; f < 4; f++)
#pragma unroll
                for (int g = 0; g < 4; g++) {
                    mma_bf16(acc[f][g], ah[f], bh[g]);
                    mma_bf16(acc[f][g], al[f], bh[g]);
                    mma_bf16(acc[f][g], ah[f], bl[g]);
                }
        }
        __syncthreads();
    }

#pragma unroll
    for (int f = 0; f < 4; f++) {
        int r0 = bm + wm * 64 + f * 16 + (lane >> 2);
#pragma unroll
        for (int half = 0; half < 2; half++) {
            int gr = r0 + half * 8;
            if (gr >= M) continue;
#pragma unroll
            for (int g = 0; g < 4; g++) {
                int col = bn + wn * 32 + g * 8 + (lane & 3) * 2;
                float v0 = acc[f][g][half * 2 + 0];
                float v1 = acc[f][g][half * 2 + 1];
                if (mode == 0) {
                    *reinterpret_cast<float2*>(out0 + (size_t)gr * 256 + col) =
                        make_float2(v0, v1);
                } else {
                    float* base = (bn == 0) ? out0 : out1;
                    int cl = col - bn;
                    *reinterpret_cast<float2*>(base + (size_t)gr * 128 + cl) =
                        make_float2(v0 + bias[col], v1 + bias[col + 1]);
                }
            }
        }
    }
}

// ---------------- CSR gather aggregation (one warp per dst node) -------------
// pass 0: h[n] = relu( dinv^2 * xw[n] + sum nrm * xw[src] + b1 )
// pass 1: a = dinv^2 * h[n] + sum nrm * h[src]; write bf16 hi/lo split directly
__global__ void __launch_bounds__(256)
k_agg_csr(int pass, const float* __restrict__ b1)
{
    const int w    = (blockIdx.x * blockDim.x + threadIdx.x) >> 5;
    const int lane = threadIdx.x & 31;
    if (w >= N_NODES) return;

    const float* __restrict__ in = pass ? g_h : g_xw;
    const float dn = g_dinv[w];
    const float dd = dn * dn;

    const float4* selfrow = reinterpret_cast<const float4*>(in + (size_t)w * 256);
    float4 s0 = selfrow[lane];
    float4 s1 = selfrow[lane + 32];
    float4 a0 = make_float4(s0.x * dd, s0.y * dd, s0.z * dd, s0.w * dd);
    float4 a1 = make_float4(s1.x * dd, s1.y * dd, s1.z * dd, s1.w * dd);

    const int st = g_off[w];
    const int en = st + g_degi[w];       // ranges disjoint, not node-ordered
    int e = st;
    // 2-edge unroll: 4 independent 16B row loads in flight per lane
    for (; e + 1 < en; e += 2) {
        int sa = g_esrc[e];
        int sc = g_esrc[e + 1];
        float na = g_dinv[sa] * dn;
        float nc = g_dinv[sc] * dn;
        const float4* ra = reinterpret_cast<const float4*>(in + (size_t)sa * 256);
        const float4* rc = reinterpret_cast<const float4*>(in + (size_t)sc * 256);
        float4 va0 = ra[lane];
        float4 va1 = ra[lane + 32];
        float4 vc0 = rc[lane];
        float4 vc1 = rc[lane + 32];
        a0.x = fmaf(na, va0.x, a0.x); a0.y = fmaf(na, va0.y, a0.y);
        a0.z = fmaf(na, va0.z, a0.z); a0.w = fmaf(na, va0.w, a0.w);
        a1.x = fmaf(na, va1.x, a1.x); a1.y = fmaf(na, va1.y, a1.y);
        a1.z = fmaf(na, va1.z, a1.z); a1.w = fmaf(na, va1.w, a1.w);
        a0.x = fmaf(nc, vc0.x, a0.x); a0.y = fmaf(nc, vc0.y, a0.y);
        a0.z = fmaf(nc, vc0.z, a0.z); a0.w = fmaf(nc, vc0.w, a0.w);
        a1.x = fmaf(nc, vc1.x, a1.x); a1.y = fmaf(nc, vc1.y, a1.y);
        a1.z = fmaf(nc, vc1.z, a1.z); a1.w = fmaf(nc, vc1.w, a1.w);
    }
    if (e < en) {
        int sa = g_esrc[e];
        float na = g_dinv[sa] * dn;
        const float4* ra = reinterpret_cast<const float4*>(in + (size_t)sa * 256);
        float4 va0 = ra[lane];
        float4 va1 = ra[lane + 32];
        a0.x = fmaf(na, va0.x, a0.x); a0.y = fmaf(na, va0.y, a0.y);
        a0.z = fmaf(na, va0.z, a0.z); a0.w = fmaf(na, va0.w, a0.w);
        a1.x = fmaf(na, va1.x, a1.x); a1.y = fmaf(na, va1.y, a1.y);
        a1.z = fmaf(na, va1.z, a1.z); a1.w = fmaf(na, va1.w, a1.w);
    }

    if (pass == 0) {
        const float4* bb = reinterpret_cast<const float4*>(b1);
        float4 b0 = bb[lane], b1v = bb[lane + 32];
        a0.x = fmaxf(a0.x + b0.x, 0.f);  a0.y = fmaxf(a0.y + b0.y, 0.f);
        a0.z = fmaxf(a0.z + b0.z, 0.f);  a0.w = fmaxf(a0.w + b0.w, 0.f);
        a1.x = fmaxf(a1.x + b1v.x, 0.f); a1.y = fmaxf(a1.y + b1v.y, 0.f);
        a1.z = fmaxf(a1.z + b1v.z, 0.f); a1.w = fmaxf(a1.w + b1v.w, 0.f);
        float4* o = reinterpret_cast<float4*>(g_h + (size_t)w * 256);
        o[lane] = a0;
        o[lane + 32] = a1;
    } else {
        __nv_bfloat162 h0a(__float2bfloat16(a0.x), __float2bfloat16(a0.y));
        __nv_bfloat162 h0b(__float2bfloat16(a0.z), __float2bfloat16(a0.w));
        __nv_bfloat162 l0a(__float2bfloat16(a0.x - __bfloat162float(h0a.x)),
                           __float2bfloat16(a0.y - __bfloat162float(h0a.y)));
        __nv_bfloat162 l0b(__float2bfloat16(a0.z - __bfloat162float(h0b.x)),
                           __float2bfloat16(a0.w - __bfloat162float(h0b.y)));
        __nv_bfloat162 h1a(__float2bfloat16(a1.x), __float2bfloat16(a1.y));
        __nv_bfloat162 h1b(__float2bfloat16(a1.z), __float2bfloat16(a1.w));
        __nv_bfloat162 l1a(__float2bfloat16(a1.x - __bfloat162float(h1a.x)),
                           __float2bfloat16(a1.y - __bfloat162float(h1a.y)));
        __nv_bfloat162 l1b(__float2bfloat16(a1.z - __bfloat162float(h1b.x)),
                           __float2bfloat16(a1.w - __bfloat162float(h1b.y)));
        __nv_bfloat162* H = reinterpret_cast<__nv_bfloat162*>(gA_hi + (size_t)w * 256);
        __nv_bfloat162* L = reinterpret_cast<__nv_bfloat162*>(gA_lo + (size_t)w * 256);
        H[lane * 2 + 0] = h0a;  H[lane * 2 + 1] = h0b;
        H[64 + lane * 2 + 0] = h1a;  H[64 + lane * 2 + 1] = h1b;
        L[lane * 2 + 0] = l0a;  L[lane * 2 + 1] = l0b;
        L[64 + lane * 2 + 0] = l1a;  L[64 + lane * 2 + 1] = l1b;
    }
}

// ---------------- launch ----------------------------------------------------
extern "C" void kernel_launch(void* const* d_in, const int* in_sizes, int n_in,
                              void* d_out, int out_size)
{
    const float* x   = (const float*)d_in[0];
    const int*   ei  = (const int*)d_in[1];
    const float* W1  = (const float*)d_in[2];
    const float* b1  = (const float*)d_in[3];
    const float* Wmu = (const float*)d_in[4];
    const float* bmu = (const float*)d_in[5];
    const float* Wls = (const float*)d_in[6];
    const float* bls = (const float*)d_in[7];
    float*       out = (float*)d_out;

    float *p_xw, *p_bcat;
    __nv_bfloat16 *pAh, *pAl, *pB1h, *pB1l, *pB2h, *pB2l;
    cudaGetSymbolAddress((void**)&p_xw,   g_xw);
    cudaGetSymbolAddress((void**)&p_bcat, g_bcat);
    cudaGetSymbolAddress((void**)&pAh,  gA_hi);
    cudaGetSymbolAddress((void**)&pAl,  gA_lo);
    cudaGetSymbolAddress((void**)&pB1h, gB1_hi);
    cudaGetSymbolAddress((void**)&pB1l, gB1_lo);
    cudaGetSymbolAddress((void**)&pB2h, gB2_hi);
    cudaGetSymbolAddress((void**)&pB2l, gB2_lo);

    cudaFuncSetAttribute(k_mma_gemm, cudaFuncAttributeMaxDynamicSharedMemorySize, SM_TOT);

    const size_t n4 = (size_t)N_NODES * HID_CH / 4;
    dim3 gemm_grid(2, (N_NODES + 127) / 128);

    // 1. CSR build + normalization (decoupled block scan; dinv fused in)
    k_zero   <<<(N_NODES + 255) / 256, 256>>>();
    k_cnt    <<<(N_EDGES + 255) / 256, 256>>>(ei);
    k_offsets<<<(N_NODES + 255) / 256, 256>>>();
    k_scatter<<<(N_EDGES + 255) / 256, 256>>>(ei);

    // 2. weight prep (merged) + x split
    k_prepW<<<(2 * 256 * 256 + 255) / 256, 256>>>(W1, Wmu, Wls, bmu, bls);
    k_split<<<(n4 + 255) / 256, 256>>>(x, n4);

    // 3. XW = x @ W1 (tensor cores)
    k_mma_gemm<<<gemm_grid, 256, SM_TOT>>>(pAh, pAl, pB1h, pB1l,
                                           N_NODES, 0, p_xw, nullptr, nullptr);

    // 4. CSR agg pass 1: h = relu(agg(xw) + b1)   (fused bias/relu/self-loop)
    k_agg_csr<<<(N_NODES * 32 + 255) / 256, 256>>>(0, b1);

    // 5. CSR agg pass 2: agg(h), written directly as bf16 hi/lo split
    k_agg_csr<<<(N_NODES * 32 + 255) / 256, 256>>>(1, nullptr);

    // 6. fused [mu|logstd] GEMM straight into d_out
    k_mma_gemm<<<gemm_grid, 256, SM_TOT>>>(pAh, pAl, pB2h, pB2l,
                                           N_NODES, 1, out, out + (size_t)N_NODES * OUT_CH,
                                           p_bcat);
}